// round 12
// baseline (speedup 1.0000x reference)
#include <cuda_runtime.h>
#include <stdint.h>

// Sparse Adagrad on GB300 (sm_103a) — single persistent kernel.
//
//   m_new[v] = m[v] + sum_i g_i^2
//   w_new[v] = w[v] - lr * (sum_i g_i) / (sqrt(m_new[v]) + eps)
//
// One kernel, two phases separated by a software grid barrier:
//   Phase B: build per-bucket linked lists, entries tagged with this launch's
//            generation: g_head64[v] = (gen<<32)|(row+1). Stale entries from
//            earlier graph replays have old tags -> read as empty. No clear
//            pass needed, ever.
//   Phase C: gather + update + write, grid-stride over all V*16 chunks
//            (the proven ~6.15 TB/s streaming shape).
// The barrier release increments g_bar_gen, which doubles as the next
// launch's generation. Grid is sized to SMs * occupancy so every block is
// wave-1 resident (spin barrier is safe without cooperative launch).
//
// Output layout: out[0:V*D] = weights_new, out[V*D:2*V*D] = moments_new.
// indices arrive as int32 (JAX x64 disabled). valid_count=200000 static.

#define EPS 1e-10f
#define D 64
#define CHUNKS 16            // D/4 float4 chunks per row
#define VALID_COUNT 200000
#define V_MAX 500000
#define N_MAX 262144

__device__ unsigned long long g_head64[V_MAX]; // (gen<<32)|(row+1); zero-init
__device__ unsigned long long g_next64[N_MAX]; // previous head value (same enc)
__device__ unsigned int g_bar;                 // barrier arrival counter (0-init)
__device__ unsigned int g_bar_gen;             // generation / epoch (0-init)

__global__ void __launch_bounds__(256)
persistent_adagrad_kernel(const float4* __restrict__ g,   // [N, 16]
                          const float4* __restrict__ w,   // [V, 16]
                          const float4* __restrict__ m,   // [V, 16]
                          const int*    __restrict__ idx, // [N]
                          const float*  __restrict__ lr_ptr,
                          float4* __restrict__ out_w,     // [V, 16]
                          float4* __restrict__ out_m,     // [V, 16]
                          int V, int nblocks)
{
    const int tid  = threadIdx.x;
    const int gtid = blockIdx.x * 256 + tid;
    const int nthreads = nblocks * 256;

    // This launch's generation. Every block reads it BEFORE arriving at the
    // barrier, and the release bump happens only after all arrivals, so all
    // blocks observe the same value.
    const unsigned int gen = *((volatile unsigned int*)&g_bar_gen);
    const unsigned long long tagbase = ((unsigned long long)gen << 32);

    // ── Phase B: build tagged linked lists over valid gradient rows ──
    for (int i = gtid; i < VALID_COUNT; i += nthreads) {
        int v = __ldg(&idx[i]);
        g_next64[i] = atomicExch(&g_head64[v],
                                 tagbase | (unsigned long long)(i + 1));
    }

    // ── Grid barrier (release also bumps gen for the next launch) ──
    __threadfence();
    __syncthreads();
    if (tid == 0) {
        unsigned int arrived = atomicAdd(&g_bar, 1u);
        if (arrived == (unsigned int)nblocks - 1u) {
            atomicExch(&g_bar, 0u);
            __threadfence();
            atomicExch(&g_bar_gen, gen + 1u);
        } else {
            while (*((volatile unsigned int*)&g_bar_gen) == gen)
                __nanosleep(64);
        }
    }
    __syncthreads();
    __threadfence();

    // ── Phase C: fused gather + update + write ──
    float lr = __ldg(lr_ptr);
    long total = (long)V * CHUNKS;
    for (long t = gtid; t < total; t += nthreads) {
        int v = (int)(t >> 4);
        int chunk = (int)(t & 15);
        long off = (long)v * CHUNKS + chunk;

        // Touch-once streaming loads (evict-first keeps L2 for g + metadata).
        float4 mv = __ldcs(&m[off]);
        float4 wv = __ldcs(&w[off]);

        unsigned long long e = g_head64[v];   // broadcast across row's lanes
        if ((unsigned int)(e >> 32) == gen && (unsigned int)e != 0u) {
            float4 sg  = make_float4(0.f, 0.f, 0.f, 0.f);
            float4 sg2 = make_float4(0.f, 0.f, 0.f, 0.f);
            do {
                int i = (int)((unsigned int)e) - 1;
                float4 gv = g[(long)i * CHUNKS + chunk];
                sg.x += gv.x;  sg.y += gv.y;  sg.z += gv.z;  sg.w += gv.w;
                sg2.x = fmaf(gv.x, gv.x, sg2.x);
                sg2.y = fmaf(gv.y, gv.y, sg2.y);
                sg2.z = fmaf(gv.z, gv.z, sg2.z);
                sg2.w = fmaf(gv.w, gv.w, sg2.w);
                e = g_next64[i];
            } while ((unsigned int)(e >> 32) == gen && (unsigned int)e != 0u);

            mv.x += sg2.x;  mv.y += sg2.y;  mv.z += sg2.z;  mv.w += sg2.w;

            wv.x -= lr * sg.x / (sqrtf(mv.x) + EPS);
            wv.y -= lr * sg.y / (sqrtf(mv.y) + EPS);
            wv.z -= lr * sg.z / (sqrtf(mv.z) + EPS);
            wv.w -= lr * sg.w / (sqrtf(mv.w) + EPS);
        }

        __stcs(&out_w[off], wv);
        __stcs(&out_m[off], mv);
    }
}

extern "C" void kernel_launch(void* const* d_in, const int* in_sizes, int n_in,
                              void* d_out, int out_size)
{
    const float* gradients = (const float*)d_in[0];   // [N, 64]
    const float* weights   = (const float*)d_in[1];   // [V, 64]
    const float* moments   = (const float*)d_in[2];   // [V, 64]
    const int*   indices   = (const int*)d_in[3];     // [N] int32
    const float* lr        = (const float*)d_in[4];   // scalar

    long VD = (long)in_sizes[1];          // V*D = 32,000,000
    int  V  = (int)(VD / D);              // 500,000
    float* out_w = (float*)d_out;
    float* out_m = (float*)d_out + VD;

    // Size the grid so every block is resident in wave 1 (barrier safety).
    int sms = 0, maxact = 0;
    cudaDeviceGetAttribute(&sms, cudaDevAttrMultiProcessorCount, 0);
    cudaOccupancyMaxActiveBlocksPerMultiprocessor(
        &maxact, persistent_adagrad_kernel, 256, 0);
    if (sms <= 0) sms = 148;
    if (maxact < 1) maxact = 1;
    int nblocks = sms * maxact;

    persistent_adagrad_kernel<<<nblocks, 256>>>((const float4*)gradients,
                                                (const float4*)weights,
                                                (const float4*)moments,
                                                indices, lr,
                                                (float4*)out_w,
                                                (float4*)out_m,
                                                V, nblocks);
}